// round 1
// baseline (speedup 1.0000x reference)
#include <cuda_runtime.h>
#include <cuda_bf16.h>
#include <math.h>

// Problem constants (fixed by the reference)
#define NB 4
#define HH 48
#define WW 48
#define CC 1024
#define COUT 512
#define GG 4
#define GC 256
#define PIX (NB * HH * WW)      // 9216
#define NOFF 72                 // G*K*K*2
#define NMASK 36                // G*K*K

// ---------------- scratch (no cudaMalloc allowed) ----------------
__device__ float g_x[PIX * CC];     // in_proj output
__device__ float g_x1[PIX * CC];    // dwconv+ln+gelu output
__device__ float g_off[PIX * NOFF];
__device__ float g_mlog[PIX * NMASK];
__device__ float g_dcn[PIX * CC];   // dcn core output

// ---------------- GEMM: C[M,N] = A[M,K] @ B[N,K]^T + bias[N] ----------------
// BM=BN=128, BK=8, 256 threads, 8x8 microtile per thread.
// M must be a multiple of 128 (always 9216 here). N,K arbitrary-ish (K%8==0).
#define BM 128
#define BN 128
#define BK 8

__global__ __launch_bounds__(256, 2)
void gemm_bias_kernel(const float* __restrict__ A, const float* __restrict__ B,
                      const float* __restrict__ bias, float* __restrict__ C,
                      int M, int N, int K) {
    __shared__ float As[BK][BM + 4];   // row stride 132 floats (528B, 16B aligned)
    __shared__ float Bs[BK][BN + 4];

    const int t  = threadIdx.x;       // 0..255
    const int tx = t & 15;
    const int ty = t >> 4;
    const int bm = blockIdx.y * BM;
    const int bn = blockIdx.x * BN;

    const int lr  = t >> 1;           // 0..127: tile row this thread loads
    const int lc4 = (t & 1) * 4;      // k offset 0 or 4

    float acc[8][8];
#pragma unroll
    for (int i = 0; i < 8; i++)
#pragma unroll
        for (int j = 0; j < 8; j++) acc[i][j] = 0.f;

    for (int k0 = 0; k0 < K; k0 += BK) {
        // Load A tile (M assumed multiple of BM)
        float4 av = *reinterpret_cast<const float4*>(A + (size_t)(bm + lr) * K + k0 + lc4);
        float4 bv = make_float4(0.f, 0.f, 0.f, 0.f);
        int brow = bn + lr;
        if (brow < N)
            bv = *reinterpret_cast<const float4*>(B + (size_t)brow * K + k0 + lc4);

        As[lc4 + 0][lr] = av.x; As[lc4 + 1][lr] = av.y;
        As[lc4 + 2][lr] = av.z; As[lc4 + 3][lr] = av.w;
        Bs[lc4 + 0][lr] = bv.x; Bs[lc4 + 1][lr] = bv.y;
        Bs[lc4 + 2][lr] = bv.z; Bs[lc4 + 3][lr] = bv.w;
        __syncthreads();

#pragma unroll
        for (int kk = 0; kk < BK; kk++) {
            float4 a0 = *reinterpret_cast<const float4*>(&As[kk][ty * 4]);
            float4 a1 = *reinterpret_cast<const float4*>(&As[kk][ty * 4 + 64]);
            float4 b0 = *reinterpret_cast<const float4*>(&Bs[kk][tx * 4]);
            float4 b1 = *reinterpret_cast<const float4*>(&Bs[kk][tx * 4 + 64]);
            float a[8] = {a0.x, a0.y, a0.z, a0.w, a1.x, a1.y, a1.z, a1.w};
            float b[8] = {b0.x, b0.y, b0.z, b0.w, b1.x, b1.y, b1.z, b1.w};
#pragma unroll
            for (int i = 0; i < 8; i++)
#pragma unroll
                for (int j = 0; j < 8; j++)
                    acc[i][j] = fmaf(a[i], b[j], acc[i][j]);
        }
        __syncthreads();
    }

#pragma unroll
    for (int i = 0; i < 8; i++) {
        int m = bm + ty * 4 + ((i < 4) ? i : 60 + i);   // i>=4 -> +64 block
#pragma unroll
        for (int j = 0; j < 8; j++) {
            int n = bn + tx * 4 + ((j < 4) ? j : 60 + j);
            if (n < N) C[(size_t)m * N + n] = acc[i][j] + bias[n];
        }
    }
}

// ---------------- depthwise conv 3x3 + LayerNorm + GELU ----------------
__global__ __launch_bounds__(256)
void dw_ln_gelu_kernel(const float* __restrict__ in, const float* __restrict__ wdw,
                       const float* __restrict__ bdw, const float* __restrict__ gamma,
                       const float* __restrict__ beta, float* __restrict__ x1) {
    const int pix = blockIdx.x;
    const int n = pix / (HH * WW);
    const int hw = pix % (HH * WW);
    const int h = hw / WW;
    const int w = hw % WW;
    const int t = threadIdx.x;

    float acc[4] = {0.f, 0.f, 0.f, 0.f};
#pragma unroll
    for (int kh = 0; kh < 3; kh++) {
        int y = h + kh - 1;
        if ((unsigned)y >= HH) continue;
#pragma unroll
        for (int kw = 0; kw < 3; kw++) {
            int x = w + kw - 1;
            if ((unsigned)x >= WW) continue;
            const float* p = in + (((size_t)n * HH + y) * WW + x) * CC;
#pragma unroll
            for (int i = 0; i < 4; i++) {
                int c = t + i * 256;
                acc[i] = fmaf(p[c], wdw[c * 9 + kh * 3 + kw], acc[i]);
            }
        }
    }

    float vals[4];
    float s = 0.f, s2 = 0.f;
#pragma unroll
    for (int i = 0; i < 4; i++) {
        int c = t + i * 256;
        float v = acc[i] + bdw[c];
        vals[i] = v;
        s += v;
        s2 = fmaf(v, v, s2);
    }

    // block reduce over 256 threads (8 warps)
    __shared__ float sh[16];
#pragma unroll
    for (int o = 16; o > 0; o >>= 1) {
        s  += __shfl_down_sync(0xFFFFFFFFu, s, o);
        s2 += __shfl_down_sync(0xFFFFFFFFu, s2, o);
    }
    int wid = t >> 5, lane = t & 31;
    if (lane == 0) { sh[wid] = s; sh[8 + wid] = s2; }
    __syncthreads();
    if (t == 0) {
        float S = 0.f, S2 = 0.f;
#pragma unroll
        for (int i = 0; i < 8; i++) { S += sh[i]; S2 += sh[8 + i]; }
        sh[0] = S; sh[8] = S2;
    }
    __syncthreads();
    float mean = sh[0] * (1.f / 1024.f);
    float var  = sh[8] * (1.f / 1024.f) - mean * mean;
    float rstd = rsqrtf(var + 1e-6f);

    float* o = x1 + (size_t)pix * CC;
#pragma unroll
    for (int i = 0; i < 4; i++) {
        int c = t + i * 256;
        float y = (vals[i] - mean) * rstd * gamma[c] + beta[c];
        float g = 0.5f * y * (1.f + erff(y * 0.70710678118654752f));
        o[c] = g;
    }
}

// ---------------- DCNv3 core: bilinear gather + softmax mask ----------------
__global__ __launch_bounds__(256)
void dcn_kernel(const float* __restrict__ x, const float* __restrict__ offs,
                const float* __restrict__ mlog, float* __restrict__ out) {
    const int b = blockIdx.x;      // pix*4 + g
    const int g = b & 3;
    const int pix = b >> 2;
    const int n = pix / (HH * WW);
    const int hw = pix % (HH * WW);
    const int h = hw / WW;
    const int w = hw % WW;
    const int c = threadIdx.x;     // 0..255 within group

    const float* mrow = mlog + (size_t)pix * NMASK + g * 9;
    const float* orow = offs + (size_t)pix * NOFF + g * 18;

    // softmax over 9 taps (redundant per thread; broadcast loads)
    float ml[9];
    float mx = -1e30f;
#pragma unroll
    for (int p = 0; p < 9; p++) { ml[p] = mrow[p]; mx = fmaxf(mx, ml[p]); }
    float se = 0.f;
#pragma unroll
    for (int p = 0; p < 9; p++) { ml[p] = expf(ml[p] - mx); se += ml[p]; }
    float inv = 1.f / se;

    const float* xg = x + g * GC + c;
    float acc = 0.f;
#pragma unroll
    for (int p = 0; p < 9; p++) {
        float ox = orow[2 * p + 0];
        float oy = orow[2 * p + 1];
        // unpadded pixel coords; tap order is kw-major: dx = p/3-1, dy = p%3-1
        float ux = (float)(w + (p / 3) - 1) + ox;
        float uy = (float)(h + (p % 3) - 1) + oy;
        float x0f = floorf(ux), y0f = floorf(uy);
        float fx = ux - x0f, fy = uy - y0f;
        int x0 = (int)x0f, y0 = (int)y0f;
        int x1i = x0 + 1, y1i = y0 + 1;

        float v00 = 0.f, v01 = 0.f, v10 = 0.f, v11 = 0.f;
        bool vx0 = (unsigned)x0 < WW, vx1 = (unsigned)x1i < WW;
        bool vy0 = (unsigned)y0 < HH, vy1 = (unsigned)y1i < HH;
        if (vy0) {
            const float* row = xg + (((size_t)n * HH + y0) * WW) * CC;
            if (vx0) v00 = row[(size_t)x0 * CC];
            if (vx1) v01 = row[(size_t)x1i * CC];
        }
        if (vy1) {
            const float* row = xg + (((size_t)n * HH + y1i) * WW) * CC;
            if (vx0) v10 = row[(size_t)x0 * CC];
            if (vx1) v11 = row[(size_t)x1i * CC];
        }
        float top = fmaf(fx, v01 - v00, v00);
        float bot = fmaf(fx, v11 - v10, v10);
        float bil = fmaf(fy, bot - top, top);
        acc = fmaf(ml[p] * inv, bil, acc);
    }
    out[(size_t)pix * CC + g * GC + c] = acc;
}

// ---------------- launch ----------------
extern "C" void kernel_launch(void* const* d_in, const int* in_sizes, int n_in,
                              void* d_out, int out_size) {
    const float* input     = (const float*)d_in[0];
    const float* w_in_proj = (const float*)d_in[1];
    const float* b_in_proj = (const float*)d_in[2];
    const float* w_dw      = (const float*)d_in[3];
    const float* b_dw      = (const float*)d_in[4];
    const float* ln_gamma  = (const float*)d_in[5];
    const float* ln_beta   = (const float*)d_in[6];
    const float* w_offset  = (const float*)d_in[7];
    const float* b_offset  = (const float*)d_in[8];
    const float* w_mask    = (const float*)d_in[9];
    const float* b_mask    = (const float*)d_in[10];
    const float* w_out     = (const float*)d_in[11];
    const float* b_out     = (const float*)d_in[12];
    float* out = (float*)d_out;

    float *x, *x1, *off, *mlog, *dcn;
    cudaGetSymbolAddress((void**)&x,    g_x);
    cudaGetSymbolAddress((void**)&x1,   g_x1);
    cudaGetSymbolAddress((void**)&off,  g_off);
    cudaGetSymbolAddress((void**)&mlog, g_mlog);
    cudaGetSymbolAddress((void**)&dcn,  g_dcn);

    // 1) x = input @ Win^T + b          (9216 x 1024 x 1024)
    gemm_bias_kernel<<<dim3(CC / BN, PIX / BM), 256>>>(input, w_in_proj, b_in_proj, x,
                                                       PIX, CC, CC);
    // 2) x1 = gelu(ln(dwconv(input)))
    dw_ln_gelu_kernel<<<PIX, 256>>>(input, w_dw, b_dw, ln_gamma, ln_beta, x1);
    // 3) offset = x1 @ Woff^T + b       (9216 x 72 x 1024)
    gemm_bias_kernel<<<dim3(1, PIX / BM), 256>>>(x1, w_offset, b_offset, off,
                                                 PIX, NOFF, CC);
    // 4) mask logits = x1 @ Wmask^T + b (9216 x 36 x 1024)
    gemm_bias_kernel<<<dim3(1, PIX / BM), 256>>>(x1, w_mask, b_mask, mlog,
                                                 PIX, NMASK, CC);
    // 5) dcn core
    dcn_kernel<<<PIX * GG, 256>>>(x, off, mlog, dcn);
    // 6) out = dcn @ Wout^T + b         (9216 x 512 x 1024)
    gemm_bias_kernel<<<dim3(COUT / BN, PIX / BM), 256>>>(dcn, w_out, b_out, out,
                                                         PIX, COUT, CC);
}

// round 4
// speedup vs baseline: 1.7176x; 1.7176x over previous
#include <cuda_runtime.h>
#include <cuda_bf16.h>
#include <math.h>
#include <stdint.h>

// ---------------- problem constants ----------------
#define NB 4
#define HH 48
#define WW 48
#define CC 1024
#define COUT 512
#define GG 4
#define GC 256
#define PIX 9216            // NB*HH*WW
#define NFUSE 128           // offset(72) + mask(36) = 108, padded to 128

// ---------------- scratch (no cudaMalloc allowed) ----------------
__device__ float g_x[PIX * CC];                 // in_proj output (fp32, gathered by dcn)
__device__ float g_om[PIX * NFUSE];             // fused offset+mask logits
__device__ __nv_bfloat16 g_in_hi[PIX * CC];
__device__ __nv_bfloat16 g_in_lo[PIX * CC];
__device__ __nv_bfloat16 g_x1_hi[PIX * CC];
__device__ __nv_bfloat16 g_x1_lo[PIX * CC];
__device__ __nv_bfloat16 g_dcn_hi[PIX * CC];
__device__ __nv_bfloat16 g_dcn_lo[PIX * CC];
__device__ __nv_bfloat16 g_win_hi[CC * CC];
__device__ __nv_bfloat16 g_win_lo[CC * CC];
__device__ __nv_bfloat16 g_wout_hi[COUT * CC];
__device__ __nv_bfloat16 g_wout_lo[COUT * CC];
__device__ __nv_bfloat16 g_wom_hi[NFUSE * CC];
__device__ __nv_bfloat16 g_wom_lo[NFUSE * CC];
__device__ float g_bom[NFUSE];

// ---------------- helpers ----------------
__device__ __forceinline__ uint32_t smem_to_u32(const void* p) {
    uint32_t a;
    asm("{ .reg .u64 t; cvta.to.shared.u64 t, %1; cvt.u32.u64 %0, t; }" : "=r"(a) : "l"(p));
    return a;
}
__device__ __forceinline__ uint32_t lds32(uint32_t addr) {
    uint32_t v;
    asm volatile("ld.shared.b32 %0, [%1];" : "=r"(v) : "r"(addr));
    return v;
}
#define STS128(a, r0, r1, r2, r3) \
    asm volatile("st.shared.v4.b32 [%0], {%1, %2, %3, %4};" \
                 :: "r"(a), "r"(r0), "r"(r1), "r"(r2), "r"(r3) : "memory")

// mma.sync m16n8k16 bf16 -> f32 (base ISA, sm_80+; works on sm_100)
__device__ __forceinline__ void mma16816(float* d, const uint32_t* a, uint32_t b0, uint32_t b1) {
    asm volatile(
        "mma.sync.aligned.m16n8k16.row.col.f32.bf16.bf16.f32 "
        "{%0,%1,%2,%3}, {%4,%5,%6,%7}, {%8,%9}, {%0,%1,%2,%3};"
        : "+f"(d[0]), "+f"(d[1]), "+f"(d[2]), "+f"(d[3])
        : "r"(a[0]), "r"(a[1]), "r"(a[2]), "r"(a[3]), "r"(b0), "r"(b1));
}

__device__ __forceinline__ void split1(float v, __nv_bfloat16& h, __nv_bfloat16& l) {
    h = __float2bfloat16(v);
    l = __float2bfloat16(v - __bfloat162float(h));
}

// ================= HMMA GEMM: C[M,N] = A @ B^T + bias =================
// A: [M,K] split bf16 (hi/lo), B: [N,K] split bf16. fp32 register accum.
// CTA tile 128x128, 8 warps (32m x 64n each), K chunk 64 (=128B rows, SW128 XOR swizzle).
#define KC 64
#define TILE_B 16384                      // 128 rows * 128 bytes
#define GEMM_SMEM (4 * TILE_B)            // Ah, Al, Bh, Bl  = 64KB

__device__ __forceinline__ void load_tile(uint32_t sdst, const __nv_bfloat16* g, int ldK, int t) {
#pragma unroll
    for (int i = 0; i < 4; i++) {
        int idx = t + i * 256;            // 0..1023 16B-chunks
        int row = idx >> 3;               // 0..127
        int q = idx & 7;                  // 0..7
        uint4 v = *reinterpret_cast<const uint4*>(g + (size_t)row * ldK + q * 8);
        uint32_t off = (uint32_t)(row * 128 + q * 16);
        uint32_t swz = off ^ ((off >> 3) & 0x70);
        STS128(sdst + swz, v.x, v.y, v.z, v.w);
    }
}

__global__ __launch_bounds__(256, 2)
void gemm_mma(const __nv_bfloat16* __restrict__ Ah, const __nv_bfloat16* __restrict__ Al,
              const __nv_bfloat16* __restrict__ Bh, const __nv_bfloat16* __restrict__ Bl,
              const float* __restrict__ bias, float* __restrict__ C, int N, int K) {
    extern __shared__ char smem[];
    const uint32_t sb = smem_to_u32(smem);
    const uint32_t sAh = sb, sAl = sb + TILE_B, sBh = sb + 2 * TILE_B, sBl = sb + 3 * TILE_B;

    const int t = threadIdx.x;
    const int lane = t & 31, w = t >> 5;
    const int wm = w >> 1;                // 0..3 -> m offset wm*32
    const int wn = w & 1;                 // 0..1 -> n offset wn*64
    const int gid = lane >> 2;            // 0..7
    const int tig = lane & 3;             // 0..3
    const uint32_t sw = (uint32_t)gid << 4;   // per-thread constant swizzle XOR

    const int bm = blockIdx.y * 128;
    const int bn = blockIdx.x * 128;

    float acc[2][8][4];
#pragma unroll
    for (int i = 0; i < 2; i++)
#pragma unroll
        for (int j = 0; j < 8; j++)
#pragma unroll
            for (int q = 0; q < 4; q++) acc[i][j][q] = 0.f;

    const __nv_bfloat16* gAh = Ah + (size_t)bm * K;
    const __nv_bfloat16* gAl = Al + (size_t)bm * K;
    const __nv_bfloat16* gBh = Bh + (size_t)bn * K;
    const __nv_bfloat16* gBl = Bl + (size_t)bn * K;

    const int NCH = K / KC;
    for (int c = 0; c < NCH; c++) {
        load_tile(sAh, gAh + c * KC, K, t);
        load_tile(sAl, gAl + c * KC, K, t);
        load_tile(sBh, gBh + c * KC, K, t);
        load_tile(sBl, gBl + c * KC, K, t);
        __syncthreads();

#pragma unroll
        for (int ks = 0; ks < 4; ks++) {
            const uint32_t ca0 = (uint32_t)((ks * 16 + tig * 2) * 2) ^ sw;       // k lo-half
            const uint32_t ca1 = (uint32_t)((ks * 16 + tig * 2 + 8) * 2) ^ sw;   // k hi-half

            uint32_t ah[2][4], al[2][4];
#pragma unroll
            for (int ms = 0; ms < 2; ms++) {
                uint32_t r0 = (uint32_t)((wm * 32 + ms * 16 + gid) * 128);
                uint32_t r1 = r0 + 8 * 128;
                ah[ms][0] = lds32(sAh + r0 + ca0);
                ah[ms][1] = lds32(sAh + r1 + ca0);
                ah[ms][2] = lds32(sAh + r0 + ca1);
                ah[ms][3] = lds32(sAh + r1 + ca1);
                al[ms][0] = lds32(sAl + r0 + ca0);
                al[ms][1] = lds32(sAl + r1 + ca0);
                al[ms][2] = lds32(sAl + r0 + ca1);
                al[ms][3] = lds32(sAl + r1 + ca1);
            }
#pragma unroll
            for (int ns = 0; ns < 8; ns++) {
                uint32_t rb = (uint32_t)((wn * 64 + ns * 8 + gid) * 128);
                uint32_t bh0 = lds32(sBh + rb + ca0);
                uint32_t bh1 = lds32(sBh + rb + ca1);
                uint32_t bl0 = lds32(sBl + rb + ca0);
                uint32_t bl1 = lds32(sBl + rb + ca1);
#pragma unroll
                for (int ms = 0; ms < 2; ms++) {
                    mma16816(acc[ms][ns], ah[ms], bh0, bh1);
                    mma16816(acc[ms][ns], ah[ms], bl0, bl1);
                    mma16816(acc[ms][ns], al[ms], bh0, bh1);
                }
            }
        }
        __syncthreads();
    }

    // epilogue: c0,c1 -> (row, col..col+1); c2,c3 -> (row+8, ...)
#pragma unroll
    for (int ms = 0; ms < 2; ms++) {
        int row = bm + wm * 32 + ms * 16 + gid;
#pragma unroll
        for (int ns = 0; ns < 8; ns++) {
            int col = bn + wn * 64 + ns * 8 + tig * 2;
            float bx = __ldg(bias + col), by = __ldg(bias + col + 1);
            float2 v0 = make_float2(acc[ms][ns][0] + bx, acc[ms][ns][1] + by);
            float2 v1 = make_float2(acc[ms][ns][2] + bx, acc[ms][ns][3] + by);
            *reinterpret_cast<float2*>(C + (size_t)row * N + col) = v0;
            *reinterpret_cast<float2*>(C + (size_t)(row + 8) * N + col) = v1;
        }
    }
}

// ================= conversion kernels =================
__global__ __launch_bounds__(256)
void split4_kernel(const float* __restrict__ src, __nv_bfloat16* __restrict__ hi,
                   __nv_bfloat16* __restrict__ lo, int n4) {
    int i = blockIdx.x * 256 + threadIdx.x;
    if (i >= n4) return;
    float4 v = reinterpret_cast<const float4*>(src)[i];
    __nv_bfloat16 h0, h1, h2, h3, l0, l1, l2, l3;
    split1(v.x, h0, l0); split1(v.y, h1, l1); split1(v.z, h2, l2); split1(v.w, h3, l3);
    __nv_bfloat162* hp = reinterpret_cast<__nv_bfloat162*>(hi) + i * 2;
    __nv_bfloat162* lp = reinterpret_cast<__nv_bfloat162*>(lo) + i * 2;
    hp[0] = __nv_bfloat162(h0, h1); hp[1] = __nv_bfloat162(h2, h3);
    lp[0] = __nv_bfloat162(l0, l1); lp[1] = __nv_bfloat162(l2, l3);
}

__global__ __launch_bounds__(256)
void build_wom_kernel(const float* __restrict__ woff, const float* __restrict__ boff,
                      const float* __restrict__ wmask, const float* __restrict__ bmask) {
    int i = blockIdx.x * 256 + threadIdx.x;   // over 128*1024
    if (i < NFUSE * CC) {
        int r = i >> 10, c = i & 1023;
        float v = 0.f;
        if (r < 72) v = woff[r * CC + c];
        else if (r < 108) v = wmask[(r - 72) * CC + c];
        __nv_bfloat16 h, l; split1(v, h, l);
        g_wom_hi[i] = h; g_wom_lo[i] = l;
    }
    if (i < NFUSE) {
        float b = 0.f;
        if (i < 72) b = boff[i];
        else if (i < 108) b = bmask[i - 72];
        g_bom[i] = b;
    }
}

// ================= depthwise conv 3x3 + LN + GELU -> split bf16 =================
__global__ __launch_bounds__(256)
void dw_ln_gelu_kernel(const float* __restrict__ in, const float* __restrict__ wdw,
                       const float* __restrict__ bdw, const float* __restrict__ gamma,
                       const float* __restrict__ beta,
                       __nv_bfloat16* __restrict__ x1h, __nv_bfloat16* __restrict__ x1l) {
    const int pix = blockIdx.x;
    const int n = pix / (HH * WW);
    const int hw = pix % (HH * WW);
    const int h = hw / WW;
    const int w = hw % WW;
    const int t = threadIdx.x;

    float acc[4] = {0.f, 0.f, 0.f, 0.f};
#pragma unroll
    for (int kh = 0; kh < 3; kh++) {
        int y = h + kh - 1;
        if ((unsigned)y >= HH) continue;
#pragma unroll
        for (int kw = 0; kw < 3; kw++) {
            int x = w + kw - 1;
            if ((unsigned)x >= WW) continue;
            const float* p = in + (((size_t)n * HH + y) * WW + x) * CC;
#pragma unroll
            for (int i = 0; i < 4; i++) {
                int c = t + i * 256;
                acc[i] = fmaf(p[c], wdw[c * 9 + kh * 3 + kw], acc[i]);
            }
        }
    }
    float vals[4], s = 0.f, s2 = 0.f;
#pragma unroll
    for (int i = 0; i < 4; i++) {
        int c = t + i * 256;
        float v = acc[i] + bdw[c];
        vals[i] = v; s += v; s2 = fmaf(v, v, s2);
    }
    __shared__ float sh[16];
#pragma unroll
    for (int o = 16; o > 0; o >>= 1) {
        s  += __shfl_down_sync(0xFFFFFFFFu, s, o);
        s2 += __shfl_down_sync(0xFFFFFFFFu, s2, o);
    }
    int wd = t >> 5, ln = t & 31;
    if (ln == 0) { sh[wd] = s; sh[8 + wd] = s2; }
    __syncthreads();
    if (t == 0) {
        float S = 0.f, S2 = 0.f;
#pragma unroll
        for (int i = 0; i < 8; i++) { S += sh[i]; S2 += sh[8 + i]; }
        sh[0] = S; sh[8] = S2;
    }
    __syncthreads();
    float mean = sh[0] * (1.f / 1024.f);
    float var  = sh[8] * (1.f / 1024.f) - mean * mean;
    float rstd = rsqrtf(var + 1e-6f);

    const size_t ob = (size_t)pix * CC;
#pragma unroll
    for (int i = 0; i < 4; i++) {
        int c = t + i * 256;
        float y = (vals[i] - mean) * rstd * gamma[c] + beta[c];
        float g = 0.5f * y * (1.f + erff(y * 0.70710678118654752f));
        __nv_bfloat16 hh, ll; split1(g, hh, ll);
        x1h[ob + c] = hh; x1l[ob + c] = ll;
    }
}

// ================= DCNv3 core -> split bf16 =================
__global__ __launch_bounds__(256)
void dcn_kernel(const float* __restrict__ x, const float* __restrict__ om,
                __nv_bfloat16* __restrict__ oh, __nv_bfloat16* __restrict__ ol) {
    const int b = blockIdx.x;      // pix*4 + g
    const int g = b & 3;
    const int pix = b >> 2;
    const int n = pix / (HH * WW);
    const int hw = pix % (HH * WW);
    const int h = hw / WW;
    const int w = hw % WW;
    const int c = threadIdx.x;

    const float* row = om + (size_t)pix * NFUSE;
    const float* mrow = row + 72 + g * 9;
    const float* orow = row + g * 18;

    float ml[9], mx = -1e30f;
#pragma unroll
    for (int p = 0; p < 9; p++) { ml[p] = mrow[p]; mx = fmaxf(mx, ml[p]); }
    float se = 0.f;
#pragma unroll
    for (int p = 0; p < 9; p++) { ml[p] = expf(ml[p] - mx); se += ml[p]; }
    float inv = 1.f / se;

    const float* xg = x + g * GC + c;
    float acc = 0.f;
#pragma unroll
    for (int p = 0; p < 9; p++) {
        float ox = orow[2 * p + 0];
        float oy = orow[2 * p + 1];
        float ux = (float)(w + (p / 3) - 1) + ox;
        float uy = (float)(h + (p % 3) - 1) + oy;
        float x0f = floorf(ux), y0f = floorf(uy);
        float fx = ux - x0f, fy = uy - y0f;
        int x0 = (int)x0f, y0 = (int)y0f;
        int x1i = x0 + 1, y1i = y0 + 1;

        float v00 = 0.f, v01 = 0.f, v10 = 0.f, v11 = 0.f;
        bool vx0 = (unsigned)x0 < WW, vx1 = (unsigned)x1i < WW;
        bool vy0 = (unsigned)y0 < HH, vy1 = (unsigned)y1i < HH;
        if (vy0) {
            const float* r0 = xg + (((size_t)n * HH + y0) * WW) * CC;
            if (vx0) v00 = r0[(size_t)x0 * CC];
            if (vx1) v01 = r0[(size_t)x1i * CC];
        }
        if (vy1) {
            const float* r1 = xg + (((size_t)n * HH + y1i) * WW) * CC;
            if (vx0) v10 = r1[(size_t)x0 * CC];
            if (vx1) v11 = r1[(size_t)x1i * CC];
        }
        float top = fmaf(fx, v01 - v00, v00);
        float bot = fmaf(fx, v11 - v10, v10);
        float bil = fmaf(fy, bot - top, top);
        acc = fmaf(ml[p] * inv, bil, acc);
    }
    __nv_bfloat16 hh, ll; split1(acc, hh, ll);
    const size_t o = (size_t)pix * CC + g * GC + c;
    oh[o] = hh; ol[o] = ll;
}

// ================= launch =================
extern "C" void kernel_launch(void* const* d_in, const int* in_sizes, int n_in,
                              void* d_out, int out_size) {
    const float* input     = (const float*)d_in[0];
    const float* w_in_proj = (const float*)d_in[1];
    const float* b_in_proj = (const float*)d_in[2];
    const float* w_dw      = (const float*)d_in[3];
    const float* b_dw      = (const float*)d_in[4];
    const float* ln_gamma  = (const float*)d_in[5];
    const float* ln_beta   = (const float*)d_in[6];
    const float* w_offset  = (const float*)d_in[7];
    const float* b_offset  = (const float*)d_in[8];
    const float* w_mask    = (const float*)d_in[9];
    const float* b_mask    = (const float*)d_in[10];
    const float* w_out     = (const float*)d_in[11];
    const float* b_out     = (const float*)d_in[12];
    float* out = (float*)d_out;

    float *x, *om, *bom;
    __nv_bfloat16 *inh, *inl, *x1h, *x1l, *dch, *dcl;
    __nv_bfloat16 *winh, *winl, *wouth, *woutl, *womh, *woml;
    cudaGetSymbolAddress((void**)&x,    g_x);
    cudaGetSymbolAddress((void**)&om,   g_om);
    cudaGetSymbolAddress((void**)&bom,  g_bom);
    cudaGetSymbolAddress((void**)&inh,  g_in_hi);
    cudaGetSymbolAddress((void**)&inl,  g_in_lo);
    cudaGetSymbolAddress((void**)&x1h,  g_x1_hi);
    cudaGetSymbolAddress((void**)&x1l,  g_x1_lo);
    cudaGetSymbolAddress((void**)&dch,  g_dcn_hi);
    cudaGetSymbolAddress((void**)&dcl,  g_dcn_lo);
    cudaGetSymbolAddress((void**)&winh, g_win_hi);
    cudaGetSymbolAddress((void**)&winl, g_win_lo);
    cudaGetSymbolAddress((void**)&wouth, g_wout_hi);
    cudaGetSymbolAddress((void**)&woutl, g_wout_lo);
    cudaGetSymbolAddress((void**)&womh, g_wom_hi);
    cudaGetSymbolAddress((void**)&woml, g_wom_lo);

    cudaFuncSetAttribute(gemm_mma, cudaFuncAttributeMaxDynamicSharedMemorySize, GEMM_SMEM);

    // conversions
    split4_kernel<<<(PIX * CC / 4 + 255) / 256, 256>>>(input, inh, inl, PIX * CC / 4);
    split4_kernel<<<(CC * CC / 4 + 255) / 256, 256>>>(w_in_proj, winh, winl, CC * CC / 4);
    split4_kernel<<<(COUT * CC / 4 + 255) / 256, 256>>>(w_out, wouth, woutl, COUT * CC / 4);
    build_wom_kernel<<<(NFUSE * CC + 255) / 256, 256>>>(w_offset, b_offset, w_mask, b_mask);

    // 1) x = input @ Win^T + b   (9216 x 1024 x 1024), fp32 out for gather
    gemm_mma<<<dim3(CC / 128, PIX / 128), 256, GEMM_SMEM>>>(inh, inl, winh, winl,
                                                            b_in_proj, x, CC, CC);
    // 2) x1 = gelu(ln(dwconv(input))) -> split bf16
    dw_ln_gelu_kernel<<<PIX, 256>>>(input, w_dw, b_dw, ln_gamma, ln_beta, x1h, x1l);
    // 3) fused offset+mask logits  (9216 x 128 x 1024)
    gemm_mma<<<dim3(1, PIX / 128), 256, GEMM_SMEM>>>(x1h, x1l, womh, woml, bom, om, NFUSE, CC);
    // 4) dcn core -> split bf16
    dcn_kernel<<<PIX * GG, 256>>>(x, om, dch, dcl);
    // 5) out = dcn @ Wout^T + b   (9216 x 512 x 1024), fp32 to d_out
    gemm_mma<<<dim3(COUT / 128, PIX / 128), 256, GEMM_SMEM>>>(dch, dcl, wouth, woutl,
                                                              b_out, out, COUT, CC);
}

// round 5
// speedup vs baseline: 3.1676x; 1.8442x over previous
#include <cuda_runtime.h>
#include <cuda_bf16.h>
#include <math.h>
#include <stdint.h>

// ---------------- problem constants ----------------
#define NB 4
#define HH 48
#define WW 48
#define CC 1024
#define COUT 512
#define GG 4
#define GC 256
#define PIX 9216            // NB*HH*WW
#define NFUSE 128           // offset(72) + mask(36) = 108, padded to 128

// ---------------- scratch (no cudaMalloc allowed) ----------------
__device__ float g_x[PIX * CC];                 // in_proj output (fp32, gathered by dcn)
__device__ float g_om[PIX * NFUSE];             // fused offset+mask logits
__device__ __nv_bfloat16 g_in_hi[PIX * CC];
__device__ __nv_bfloat16 g_in_lo[PIX * CC];
__device__ __nv_bfloat16 g_x1_hi[PIX * CC];
__device__ __nv_bfloat16 g_x1_lo[PIX * CC];
__device__ __nv_bfloat16 g_dcn_hi[PIX * CC];
__device__ __nv_bfloat16 g_dcn_lo[PIX * CC];
__device__ __nv_bfloat16 g_win_hi[CC * CC];
__device__ __nv_bfloat16 g_win_lo[CC * CC];
__device__ __nv_bfloat16 g_wout_hi[COUT * CC];
__device__ __nv_bfloat16 g_wout_lo[COUT * CC];
__device__ __nv_bfloat16 g_wom_hi[NFUSE * CC];
__device__ __nv_bfloat16 g_wom_lo[NFUSE * CC];
__device__ float g_bom[NFUSE];
__device__ float g_wdwt[9 * CC];                // transposed depthwise weights [tap][C]

// ---------------- helpers ----------------
__device__ __forceinline__ uint32_t smem_to_u32(const void* p) {
    uint32_t a;
    asm("{ .reg .u64 t; cvta.to.shared.u64 t, %1; cvt.u32.u64 %0, t; }" : "=r"(a) : "l"(p));
    return a;
}
__device__ __forceinline__ void cpa16(uint32_t s, const void* g) {
    asm volatile("cp.async.cg.shared.global [%0], [%1], 16;" :: "r"(s), "l"(g));
}
#define CP_COMMIT() asm volatile("cp.async.commit_group;" ::: "memory")
#define CP_WAIT1()  asm volatile("cp.async.wait_group 1;" ::: "memory")
#define CP_WAIT0()  asm volatile("cp.async.wait_group 0;" ::: "memory")
#define LDSM4(r0, r1, r2, r3, addr) \
    asm volatile("ldmatrix.sync.aligned.m8n8.x4.shared.b16 {%0,%1,%2,%3}, [%4];" \
                 : "=r"(r0), "=r"(r1), "=r"(r2), "=r"(r3) : "r"(addr))

// mma.sync m16n8k16 bf16 -> f32 (base ISA, works on sm_100)
__device__ __forceinline__ void mma16816(float* d, const uint32_t* a, uint32_t b0, uint32_t b1) {
    asm volatile(
        "mma.sync.aligned.m16n8k16.row.col.f32.bf16.bf16.f32 "
        "{%0,%1,%2,%3}, {%4,%5,%6,%7}, {%8,%9}, {%0,%1,%2,%3};"
        : "+f"(d[0]), "+f"(d[1]), "+f"(d[2]), "+f"(d[3])
        : "r"(a[0]), "r"(a[1]), "r"(a[2]), "r"(a[3]), "r"(b0), "r"(b1));
}

__device__ __forceinline__ void split1(float v, __nv_bfloat16& h, __nv_bfloat16& l) {
    h = __float2bfloat16(v);
    l = __float2bfloat16(v - __bfloat162float(h));
}

// ================= HMMA GEMM: C[M,N] = A @ B^T + bias =================
// A: [M,K] split bf16 (hi/lo), B: [N,K] split bf16. fp32 register accum.
// CTA tile 128x128, 8 warps (32m x 64n each), K chunk 64 (128B rows, XOR swizzle).
// 2-stage cp.async pipeline, ldmatrix fragment loads.
#define KC 64
#define TILE_B 16384                       // 128 rows * 128 bytes
#define STAGE_B (4 * TILE_B)               // Ah, Al, Bh, Bl tiles
#define GEMM_SMEM (2 * STAGE_B)            // 128KB

__global__ __launch_bounds__(256, 1)
void gemm_mma(const __nv_bfloat16* __restrict__ Ah, const __nv_bfloat16* __restrict__ Al,
              const __nv_bfloat16* __restrict__ Bh, const __nv_bfloat16* __restrict__ Bl,
              const float* __restrict__ bias, float* __restrict__ C, int N, int K) {
    extern __shared__ char smem[];
    const uint32_t sb = smem_to_u32(smem);

    const int t = threadIdx.x;
    const int lane = t & 31, w = t >> 5;
    const int wm = w >> 1;                 // m offset wm*32
    const int wn = w & 1;                  // n offset wn*64
    const int gid = lane >> 2;
    const int tig = lane & 3;

    const int bm = blockIdx.y * 128;
    const int bn = blockIdx.x * 128;

    // ---- loader per-thread precompute (4 chunks of 16B per tile) ----
    uint32_t ld_dst[4];
    uint32_t ld_src[4];                    // byte offset within [128, KC] slab start
#pragma unroll
    for (int i = 0; i < 4; i++) {
        int idx = t + i * 256;
        int row = idx >> 3, q = idx & 7;
        uint32_t off = (uint32_t)(row * 128 + q * 16);
        ld_dst[i] = off ^ ((uint32_t)(row & 7) << 4);
        ld_src[i] = (uint32_t)row * (uint32_t)K * 2u + (uint32_t)q * 16u;
    }
    const char* gsrc[4] = {
        (const char*)(Ah + (size_t)bm * K), (const char*)(Al + (size_t)bm * K),
        (const char*)(Bh + (size_t)bn * K), (const char*)(Bl + (size_t)bn * K)};

    // ---- fragment address precompute ----
    const int rA = lane & 7, tA = lane >> 3;
    const uint32_t rowA = (uint32_t)(wm * 32 + (tA & 1) * 8 + rA) * 128;
    const uint32_t kselA = (uint32_t)(tA >> 1) * 16;
    const uint32_t swA = (uint32_t)rA << 4;
    uint32_t rowB[4];
#pragma unroll
    for (int np = 0; np < 4; np++)
        rowB[np] = (uint32_t)(wn * 64 + np * 16 + ((lane >> 4) & 1) * 8 + (lane & 7)) * 128;
    const uint32_t kselB = (uint32_t)((lane >> 3) & 1) * 16;
    const uint32_t swB = (uint32_t)(lane & 7) << 4;

    float acc[2][8][4];
#pragma unroll
    for (int i = 0; i < 2; i++)
#pragma unroll
        for (int j = 0; j < 8; j++)
#pragma unroll
            for (int q = 0; q < 4; q++) acc[i][j][q] = 0.f;

    const int NCH = K / KC;

    // prefetch chunk 0 -> stage 0
#pragma unroll
    for (int tile = 0; tile < 4; tile++) {
        uint32_t base = sb + tile * TILE_B;
        const char* g = gsrc[tile];
#pragma unroll
        for (int i = 0; i < 4; i++) cpa16(base + ld_dst[i], g + ld_src[i]);
    }
    CP_COMMIT();

    for (int c = 0; c < NCH; c++) {
        const int s = c & 1;
        if (c + 1 < NCH) {
            const uint32_t sb2 = sb + (uint32_t)(s ^ 1) * STAGE_B;
            const uint32_t coff = (uint32_t)(c + 1) * KC * 2u;
#pragma unroll
            for (int tile = 0; tile < 4; tile++) {
                uint32_t base = sb2 + tile * TILE_B;
                const char* g = gsrc[tile] + coff;
#pragma unroll
                for (int i = 0; i < 4; i++) cpa16(base + ld_dst[i], g + ld_src[i]);
            }
            CP_COMMIT();
            CP_WAIT1();
        } else {
            CP_WAIT0();
        }
        __syncthreads();

        const uint32_t stg = sb + (uint32_t)s * STAGE_B;
        const uint32_t sAh = stg, sAl = stg + TILE_B, sBh = stg + 2 * TILE_B, sBl = stg + 3 * TILE_B;

#pragma unroll
        for (int ks = 0; ks < 4; ks++) {
            const uint32_t kA = ((uint32_t)(ks * 32) + kselA) ^ swA;
            const uint32_t kB = ((uint32_t)(ks * 32) + kselB) ^ swB;

            uint32_t aH[2][4], aL[2][4];
            LDSM4(aH[0][0], aH[0][1], aH[0][2], aH[0][3], sAh + rowA + kA);
            LDSM4(aH[1][0], aH[1][1], aH[1][2], aH[1][3], sAh + rowA + 2048 + kA);
            LDSM4(aL[0][0], aL[0][1], aL[0][2], aL[0][3], sAl + rowA + kA);
            LDSM4(aL[1][0], aL[1][1], aL[1][2], aL[1][3], sAl + rowA + 2048 + kA);

#pragma unroll
            for (int np = 0; np < 4; np++) {
                uint32_t bh[4], bl[4];
                LDSM4(bh[0], bh[1], bh[2], bh[3], sBh + rowB[np] + kB);
                LDSM4(bl[0], bl[1], bl[2], bl[3], sBl + rowB[np] + kB);
#pragma unroll
                for (int half = 0; half < 2; half++) {
                    const int ns = np * 2 + half;
                    const uint32_t bh0 = bh[half * 2], bh1 = bh[half * 2 + 1];
                    const uint32_t bl0 = bl[half * 2], bl1 = bl[half * 2 + 1];
#pragma unroll
                    for (int ms = 0; ms < 2; ms++) {
                        mma16816(acc[ms][ns], aH[ms], bh0, bh1);
                        mma16816(acc[ms][ns], aH[ms], bl0, bl1);
                        mma16816(acc[ms][ns], aL[ms], bh0, bh1);
                    }
                }
            }
        }
        __syncthreads();
    }

    // epilogue (same mapping as validated R4 kernel)
#pragma unroll
    for (int ms = 0; ms < 2; ms++) {
        int row = bm + wm * 32 + ms * 16 + gid;
#pragma unroll
        for (int ns = 0; ns < 8; ns++) {
            int col = bn + wn * 64 + ns * 8 + tig * 2;
            float bx = __ldg(bias + col), by = __ldg(bias + col + 1);
            float2 v0 = make_float2(acc[ms][ns][0] + bx, acc[ms][ns][1] + by);
            float2 v1 = make_float2(acc[ms][ns][2] + bx, acc[ms][ns][3] + by);
            *reinterpret_cast<float2*>(C + (size_t)row * N + col) = v0;
            *reinterpret_cast<float2*>(C + (size_t)(row + 8) * N + col) = v1;
        }
    }
}

// ================= conversion kernels =================
__global__ __launch_bounds__(256)
void split4_kernel(const float* __restrict__ src, __nv_bfloat16* __restrict__ hi,
                   __nv_bfloat16* __restrict__ lo, int n4) {
    int i = blockIdx.x * 256 + threadIdx.x;
    if (i >= n4) return;
    float4 v = reinterpret_cast<const float4*>(src)[i];
    __nv_bfloat16 h0, h1, h2, h3, l0, l1, l2, l3;
    split1(v.x, h0, l0); split1(v.y, h1, l1); split1(v.z, h2, l2); split1(v.w, h3, l3);
    __nv_bfloat162* hp = reinterpret_cast<__nv_bfloat162*>(hi) + i * 2;
    __nv_bfloat162* lp = reinterpret_cast<__nv_bfloat162*>(lo) + i * 2;
    hp[0] = __nv_bfloat162(h0, h1); hp[1] = __nv_bfloat162(h2, h3);
    lp[0] = __nv_bfloat162(l0, l1); lp[1] = __nv_bfloat162(l2, l3);
}

__global__ __launch_bounds__(256)
void build_wom_kernel(const float* __restrict__ woff, const float* __restrict__ boff,
                      const float* __restrict__ wmask, const float* __restrict__ bmask,
                      const float* __restrict__ wdw) {
    int i = blockIdx.x * 256 + threadIdx.x;   // 512*256 = 131072 threads
    if (i < NFUSE * CC) {
        int r = i >> 10, c = i & 1023;
        float v = 0.f;
        if (r < 72) v = woff[r * CC + c];
        else if (r < 108) v = wmask[(r - 72) * CC + c];
        __nv_bfloat16 h, l; split1(v, h, l);
        g_wom_hi[i] = h; g_wom_lo[i] = l;
    }
    if (i < NFUSE) {
        float b = 0.f;
        if (i < 72) b = boff[i];
        else if (i < 108) b = bmask[i - 72];
        g_bom[i] = b;
    }
    if (i < 9 * CC) {
        int k = i >> 10, c = i & 1023;
        g_wdwt[k * CC + c] = wdw[c * 9 + k];
    }
}

// ================= depthwise conv 3x3 + LN + GELU -> split bf16 =================
__global__ __launch_bounds__(256)
void dw_ln_gelu_kernel(const float* __restrict__ in,
                       const float* __restrict__ bdw, const float* __restrict__ gamma,
                       const float* __restrict__ beta,
                       __nv_bfloat16* __restrict__ x1h, __nv_bfloat16* __restrict__ x1l) {
    const int pix = blockIdx.x;
    const int n = pix / (HH * WW);
    const int hw = pix % (HH * WW);
    const int h = hw / WW;
    const int w = hw % WW;
    const int t = threadIdx.x;
    const int c4 = t * 4;

    float4 acc = make_float4(0.f, 0.f, 0.f, 0.f);
#pragma unroll
    for (int kh = 0; kh < 3; kh++) {
        int y = h + kh - 1;
        if ((unsigned)y >= HH) continue;
#pragma unroll
        for (int kw = 0; kw < 3; kw++) {
            int x = w + kw - 1;
            if ((unsigned)x >= WW) continue;
            const float4 pv = *reinterpret_cast<const float4*>(
                in + (((size_t)n * HH + y) * WW + x) * CC + c4);
            const float4 wv = *reinterpret_cast<const float4*>(
                g_wdwt + (kh * 3 + kw) * CC + c4);
            acc.x = fmaf(pv.x, wv.x, acc.x);
            acc.y = fmaf(pv.y, wv.y, acc.y);
            acc.z = fmaf(pv.z, wv.z, acc.z);
            acc.w = fmaf(pv.w, wv.w, acc.w);
        }
    }
    const float4 bv = *reinterpret_cast<const float4*>(bdw + c4);
    float vals[4] = {acc.x + bv.x, acc.y + bv.y, acc.z + bv.z, acc.w + bv.w};
    float s = 0.f, s2 = 0.f;
#pragma unroll
    for (int i = 0; i < 4; i++) { s += vals[i]; s2 = fmaf(vals[i], vals[i], s2); }

    __shared__ float sh[16];
#pragma unroll
    for (int o = 16; o > 0; o >>= 1) {
        s  += __shfl_down_sync(0xFFFFFFFFu, s, o);
        s2 += __shfl_down_sync(0xFFFFFFFFu, s2, o);
    }
    int wd = t >> 5, ln = t & 31;
    if (ln == 0) { sh[wd] = s; sh[8 + wd] = s2; }
    __syncthreads();
    if (t == 0) {
        float S = 0.f, S2 = 0.f;
#pragma unroll
        for (int i = 0; i < 8; i++) { S += sh[i]; S2 += sh[8 + i]; }
        sh[0] = S; sh[8] = S2;
    }
    __syncthreads();
    float mean = sh[0] * (1.f / 1024.f);
    float var  = sh[8] * (1.f / 1024.f) - mean * mean;
    float rstd = rsqrtf(var + 1e-6f);

    const float4 gv = *reinterpret_cast<const float4*>(gamma + c4);
    const float4 btv = *reinterpret_cast<const float4*>(beta + c4);
    const float ga[4] = {gv.x, gv.y, gv.z, gv.w};
    const float be[4] = {btv.x, btv.y, btv.z, btv.w};

    __nv_bfloat16 hh[4], ll[4];
#pragma unroll
    for (int i = 0; i < 4; i++) {
        float y = (vals[i] - mean) * rstd * ga[i] + be[i];
        float g = 0.5f * y * (1.f + erff(y * 0.70710678118654752f));
        split1(g, hh[i], ll[i]);
    }
    const size_t ob = (size_t)pix * CC + c4;
    __nv_bfloat162* hp = reinterpret_cast<__nv_bfloat162*>(x1h + ob);
    __nv_bfloat162* lp = reinterpret_cast<__nv_bfloat162*>(x1l + ob);
    hp[0] = __nv_bfloat162(hh[0], hh[1]); hp[1] = __nv_bfloat162(hh[2], hh[3]);
    lp[0] = __nv_bfloat162(ll[0], ll[1]); lp[1] = __nv_bfloat162(ll[2], ll[3]);
}

// ================= DCNv3 core -> split bf16 (float4 per thread) =================
__global__ __launch_bounds__(256)
void dcn_kernel(const float* __restrict__ x, const float* __restrict__ om,
                __nv_bfloat16* __restrict__ oh, __nv_bfloat16* __restrict__ ol) {
    const int pix = blockIdx.x;
    const int n = pix / (HH * WW);
    const int hw = pix % (HH * WW);
    const int h = hw / WW;
    const int w = hw % WW;
    const int t = threadIdx.x;
    const int g = t >> 6;             // 4 groups x 64 threads
    const int ci = (t & 63) << 2;     // 4 channels per thread

    const float* row = om + (size_t)pix * NFUSE;
    const float* mrow = row + 72 + g * 9;
    const float* orow = row + g * 18;

    float ml[9], mx = -1e30f;
#pragma unroll
    for (int p = 0; p < 9; p++) { ml[p] = mrow[p]; mx = fmaxf(mx, ml[p]); }
    float se = 0.f;
#pragma unroll
    for (int p = 0; p < 9; p++) { ml[p] = expf(ml[p] - mx); se += ml[p]; }
    float inv = 1.f / se;

    const float* xg = x + g * GC + ci;
    float a0 = 0.f, a1 = 0.f, a2 = 0.f, a3 = 0.f;
#pragma unroll
    for (int p = 0; p < 9; p++) {
        float ox = orow[2 * p + 0];
        float oy = orow[2 * p + 1];
        float ux = (float)(w + (p / 3) - 1) + ox;
        float uy = (float)(h + (p % 3) - 1) + oy;
        float x0f = floorf(ux), y0f = floorf(uy);
        float fx = ux - x0f, fy = uy - y0f;
        int x0 = (int)x0f, y0 = (int)y0f;
        int x1i = x0 + 1, y1i = y0 + 1;

        const float4 z = make_float4(0.f, 0.f, 0.f, 0.f);
        float4 v00 = z, v01 = z, v10 = z, v11 = z;
        bool vx0 = (unsigned)x0 < WW, vx1 = (unsigned)x1i < WW;
        if ((unsigned)y0 < HH) {
            const float* r0 = xg + (((size_t)n * HH + y0) * WW) * CC;
            if (vx0) v00 = *reinterpret_cast<const float4*>(r0 + (size_t)x0 * CC);
            if (vx1) v01 = *reinterpret_cast<const float4*>(r0 + (size_t)x1i * CC);
        }
        if ((unsigned)y1i < HH) {
            const float* r1 = xg + (((size_t)n * HH + y1i) * WW) * CC;
            if (vx0) v10 = *reinterpret_cast<const float4*>(r1 + (size_t)x0 * CC);
            if (vx1) v11 = *reinterpret_cast<const float4*>(r1 + (size_t)x1i * CC);
        }
        float wt = ml[p] * inv;
        float t0, b0v;
        t0 = fmaf(fx, v01.x - v00.x, v00.x); b0v = fmaf(fx, v11.x - v10.x, v10.x);
        a0 = fmaf(wt, fmaf(fy, b0v - t0, t0), a0);
        t0 = fmaf(fx, v01.y - v00.y, v00.y); b0v = fmaf(fx, v11.y - v10.y, v10.y);
        a1 = fmaf(wt, fmaf(fy, b0v - t0, t0), a1);
        t0 = fmaf(fx, v01.z - v00.z, v00.z); b0v = fmaf(fx, v11.z - v10.z, v10.z);
        a2 = fmaf(wt, fmaf(fy, b0v - t0, t0), a2);
        t0 = fmaf(fx, v01.w - v00.w, v00.w); b0v = fmaf(fx, v11.w - v10.w, v10.w);
        a3 = fmaf(wt, fmaf(fy, b0v - t0, t0), a3);
    }
    __nv_bfloat16 h0, h1, h2, h3, l0, l1, l2, l3;
    split1(a0, h0, l0); split1(a1, h1, l1); split1(a2, h2, l2); split1(a3, h3, l3);
    const size_t o = (size_t)pix * CC + g * GC + ci;
    __nv_bfloat162* hp = reinterpret_cast<__nv_bfloat162*>(oh + o);
    __nv_bfloat162* lp = reinterpret_cast<__nv_bfloat162*>(ol + o);
    hp[0] = __nv_bfloat162(h0, h1); hp[1] = __nv_bfloat162(h2, h3);
    lp[0] = __nv_bfloat162(l0, l1); lp[1] = __nv_bfloat162(l2, l3);
}

// ================= launch =================
extern "C" void kernel_launch(void* const* d_in, const int* in_sizes, int n_in,
                              void* d_out, int out_size) {
    const float* input     = (const float*)d_in[0];
    const float* w_in_proj = (const float*)d_in[1];
    const float* b_in_proj = (const float*)d_in[2];
    const float* w_dw      = (const float*)d_in[3];
    const float* b_dw      = (const float*)d_in[4];
    const float* ln_gamma  = (const float*)d_in[5];
    const float* ln_beta   = (const float*)d_in[6];
    const float* w_offset  = (const float*)d_in[7];
    const float* b_offset  = (const float*)d_in[8];
    const float* w_mask    = (const float*)d_in[9];
    const float* b_mask    = (const float*)d_in[10];
    const float* w_out     = (const float*)d_in[11];
    const float* b_out     = (const float*)d_in[12];
    float* out = (float*)d_out;

    float *x, *om, *bom;
    __nv_bfloat16 *inh, *inl, *x1h, *x1l, *dch, *dcl;
    __nv_bfloat16 *winh, *winl, *wouth, *woutl, *womh, *woml;
    cudaGetSymbolAddress((void**)&x,    g_x);
    cudaGetSymbolAddress((void**)&om,   g_om);
    cudaGetSymbolAddress((void**)&bom,  g_bom);
    cudaGetSymbolAddress((void**)&inh,  g_in_hi);
    cudaGetSymbolAddress((void**)&inl,  g_in_lo);
    cudaGetSymbolAddress((void**)&x1h,  g_x1_hi);
    cudaGetSymbolAddress((void**)&x1l,  g_x1_lo);
    cudaGetSymbolAddress((void**)&dch,  g_dcn_hi);
    cudaGetSymbolAddress((void**)&dcl,  g_dcn_lo);
    cudaGetSymbolAddress((void**)&winh, g_win_hi);
    cudaGetSymbolAddress((void**)&winl, g_win_lo);
    cudaGetSymbolAddress((void**)&wouth, g_wout_hi);
    cudaGetSymbolAddress((void**)&woutl, g_wout_lo);
    cudaGetSymbolAddress((void**)&womh, g_wom_hi);
    cudaGetSymbolAddress((void**)&woml, g_wom_lo);

    cudaFuncSetAttribute(gemm_mma, cudaFuncAttributeMaxDynamicSharedMemorySize, GEMM_SMEM);

    // conversions
    split4_kernel<<<(PIX * CC / 4 + 255) / 256, 256>>>(input, inh, inl, PIX * CC / 4);
    split4_kernel<<<(CC * CC / 4 + 255) / 256, 256>>>(w_in_proj, winh, winl, CC * CC / 4);
    split4_kernel<<<(COUT * CC / 4 + 255) / 256, 256>>>(w_out, wouth, woutl, COUT * CC / 4);
    build_wom_kernel<<<512, 256>>>(w_offset, b_offset, w_mask, b_mask, w_dw);

    // 1) x = input @ Win^T + b   (9216 x 1024 x 1024), fp32 out for gather
    gemm_mma<<<dim3(CC / 128, PIX / 128), 256, GEMM_SMEM>>>(inh, inl, winh, winl,
                                                            b_in_proj, x, CC, CC);
    // 2) x1 = gelu(ln(dwconv(input))) -> split bf16
    dw_ln_gelu_kernel<<<PIX, 256>>>(input, b_dw, ln_gamma, ln_beta, x1h, x1l);
    // 3) fused offset+mask logits  (9216 x 128 x 1024)
    gemm_mma<<<dim3(1, PIX / 128), 256, GEMM_SMEM>>>(x1h, x1l, womh, woml, bom, om, NFUSE, CC);
    // 4) dcn core -> split bf16
    dcn_kernel<<<PIX, 256>>>(x, om, dch, dcl);
    // 5) out = dcn @ Wout^T + b   (9216 x 512 x 1024), fp32 to d_out
    gemm_mma<<<dim3(COUT / 128, PIX / 128), 256, GEMM_SMEM>>>(dch, dcl, wouth, woutl,
                                                              b_out, out, COUT, CC);
}